// round 6
// baseline (speedup 1.0000x reference)
#include <cuda_runtime.h>
#include <cuda_fp16.h>
#include <cstdint>
#include <cstddef>

// ==========================================================================
// TruncatedMLP fused edge MLP for GB300 (sm_103a harness, base sm_103 PTX)
//   tcgen05 is NOT available (harness compiles via compute_103 -> no 'a'
//   features). Tensor cores are used via warp-level mma.sync m16n8k16
//   (f32.f16.f16.f32) + ldmatrix, which compile on the base target.
//
//   K1: mlp_src = src_feat @ w_src^T ; mlp_dst = dst_feat @ w_dst^T + b1
//       -> fp16 scratch tables (L2-resident for the edge gather), frag->global.
//   K2: out = LN( SiLU(efeat@w_e^T + gather_src + gather_dst) @ w2^T + b2 )
//       persistent; D round-trips through XOR-swizzled fp32 smem; next-tile
//       efeat fill overlapped with the gather phase.
// ==========================================================================

#define HID 128
#define MAX_NODES_PAD 131072

__device__ __align__(256) __half g_srcp[(size_t)MAX_NODES_PAD * HID];
__device__ __align__(256) __half g_dstp[(size_t)MAX_NODES_PAD * HID];

// ---------------- helpers ----------------
__device__ __forceinline__ uint32_t smem_u32(const void* p) {
    uint32_t a;
    asm("{ .reg .u64 t; cvta.to.shared.u64 t, %1; cvt.u32.u64 %0, t; }" : "=r"(a) : "l"(p));
    return a;
}

#define LDSM4(r, addr)                                                              \
    asm volatile("ldmatrix.sync.aligned.m8n8.x4.shared.b16 {%0,%1,%2,%3}, [%4];"    \
        : "=r"((r)[0]), "=r"((r)[1]), "=r"((r)[2]), "=r"((r)[3]) : "r"(addr))

#define MMA16816(d, a, b0, b1)                                                      \
    asm volatile("mma.sync.aligned.m16n8k16.row.col.f32.f16.f16.f32 "               \
        "{%0,%1,%2,%3}, {%4,%5,%6,%7}, {%8,%9}, {%0,%1,%2,%3};"                     \
        : "+f"((d)[0]), "+f"((d)[1]), "+f"((d)[2]), "+f"((d)[3])                    \
        : "r"((a)[0]), "r"((a)[1]), "r"((a)[2]), "r"((a)[3]), "r"(b0), "r"(b1))

#define STSV2(addr, x, y)                                                           \
    asm volatile("st.shared.v2.f32 [%0], {%1,%2};" :: "r"(addr), "f"(x), "f"(y) : "memory")

__device__ __forceinline__ uint32_t pack_h2(float a, float b) {
    __half2 h = __floats2half2_rn(a, b);
    return *reinterpret_cast<uint32_t*>(&h);
}

__device__ __forceinline__ float silu_f(float x) {
    float t;
    asm("ex2.approx.f32 %0, %1;" : "=f"(t) : "f"(-1.4426950408889634f * x));
    float d = 1.0f + t;
    float r;
    asm("rcp.approx.f32 %0, %1;" : "=f"(r) : "f"(d));
    return x * r;
}

// Blocked SW128 fp16 tile: element (row, col) with col in halves (0..127).
// atom = (row>>3) + (col>>6)*16 ; inner = (row&7)*128 + (col&63)*2 ;
// byte off = atom*1024 + inner ; off ^= (off>>3)&0x70.
// 16B-unit address (col8 = col/8, 0..15):
__device__ __forceinline__ uint32_t sw_off(int row, int col8) {
    uint32_t off = (uint32_t)(((row >> 3) + (col8 >> 3) * 16) * 1024
                              + (row & 7) * 128 + (col8 & 7) * 16);
    return off ^ ((off >> 3) & 0x70);
}

// D (fp32 128x128) smem layout, conflict-free for frag st.v2 and row ld.v4:
// byte addr = r*512 + (((c>>2) ^ (r&7)) << 4) + (c&3)*4
__device__ __forceinline__ uint32_t dsw(int r, int c) {
    return (uint32_t)(r * 512 + ((((c >> 2) ^ (r & 7)) & 31) << 4) + (c & 3) * 4);
}

// Fill a 128x128 fp16 blocked SW128 smem tile from row-major fp32 (ld=128).
__device__ __forceinline__ void fill_tile(char* tile, const float* __restrict__ gsrc,
                                          int row0, int max_row, int tid) {
#pragma unroll
    for (int j = 0; j < 8; j++) {
        int v = j * 512 + tid;
        int row = v >> 5;         // 0..127
        int c4  = v & 31;         // float4 index within row
        int r = row0 + row;
        if (r > max_row) r = max_row;
        float4 f = reinterpret_cast<const float4*>(gsrc + (size_t)r * HID)[c4];
        uint32_t u0 = pack_h2(f.x, f.y);
        uint32_t u1 = pack_h2(f.z, f.w);
        uint32_t off = (uint32_t)(((row >> 3) + (c4 >> 4) * 16) * 1024
                                  + (row & 7) * 128 + (c4 & 15) * 8);
        off ^= (off >> 3) & 0x70;
        *reinterpret_cast<uint64_t*>(tile + off) = ((uint64_t)u1 << 32) | u0;
    }
}

// Warp GEMM: 16 rows x 64 cols, K=128. A tile at aoff, W tile at woff (both
// blocked smem). acc[32] = 8 n-tiles x 4 regs. Frag rows: m0 (lane-mapped).
__device__ __forceinline__ void warp_gemm(uint32_t sbase, uint32_t aoff, uint32_t woff,
                                          int m0, int n0w, int i, int j, float* acc) {
#pragma unroll
    for (int z = 0; z < 32; z++) acc[z] = 0.0f;
    const int arow = m0 + i + (j & 1) * 8;
    const int brow_i = i + (j >> 1) * 8;
#pragma unroll
    for (int ks = 0; ks < 8; ks++) {
        uint32_t a[4];
        LDSM4(a, sbase + aoff + sw_off(arow, ks * 2 + (j >> 1)));
#pragma unroll
        for (int ntp = 0; ntp < 4; ntp++) {
            uint32_t b[4];
            LDSM4(b, sbase + woff + sw_off(n0w + ntp * 16 + brow_i, ks * 2 + (j & 1)));
            MMA16816(acc + ntp * 8,     a, b[0], b[1]);
            MMA16816(acc + ntp * 8 + 4, a, b[2], b[3]);
        }
    }
}

// ==========================================================================
// K1: node projections -> fp16 scratch tables (frag -> global epilogue)
// ==========================================================================
#define S1_B1 0
#define S1_WS 1024
#define S1_WD 33792
#define S1_AS 66560
#define S1_AD 99328
#define SMEM1 132096

extern "C" __global__ void __launch_bounds__(512, 1)
k1_nodes(const float* __restrict__ src_feat, const float* __restrict__ dst_feat,
         const float* __restrict__ w_src, const float* __restrict__ w_dst,
         const float* __restrict__ b1, int Nn) {
    extern __shared__ char smem[];
    const int tid = threadIdx.x;
    const int w = tid >> 5, lane = tid & 31;
    uint32_t sbase = smem_u32(smem);

    for (int q = tid; q < HID; q += 512)
        reinterpret_cast<float*>(smem + S1_B1)[q] = b1[q];
    const int n0 = blockIdx.x << 7;
    fill_tile(smem + S1_WS, w_src, 0, HID - 1, tid);
    fill_tile(smem + S1_WD, w_dst, 0, HID - 1, tid);
    fill_tile(smem + S1_AS, src_feat, n0, Nn - 1, tid);
    fill_tile(smem + S1_AD, dst_feat, n0, Nn - 1, tid);
    __syncthreads();

    const int gID = lane >> 2, tig = lane & 3;
    const int i = lane & 7, j = lane >> 3;
    const int m0 = (w & 7) * 16, n0w = (w >> 3) * 64;

    float2 b1v[8];
#pragma unroll
    for (int nt = 0; nt < 8; nt++) {
        int c = n0w + nt * 8 + 2 * tig;
        b1v[nt] = *reinterpret_cast<const float2*>(smem + S1_B1 + c * 4);
    }

    const int node0 = n0 + m0 + gID;   // writes to padded tail are scratch
    float acc[32];

    // ---- src projection ----
    warp_gemm(sbase, S1_AS, S1_WS, m0, n0w, i, j, acc);
#pragma unroll
    for (int nt = 0; nt < 8; nt++) {
        int c = n0w + nt * 8 + 2 * tig;
        *reinterpret_cast<uint32_t*>(g_srcp + (size_t)node0 * HID + c) =
            pack_h2(acc[nt * 4 + 0], acc[nt * 4 + 1]);
        *reinterpret_cast<uint32_t*>(g_srcp + (size_t)(node0 + 8) * HID + c) =
            pack_h2(acc[nt * 4 + 2], acc[nt * 4 + 3]);
    }

    // ---- dst projection (+b1) ----
    warp_gemm(sbase, S1_AD, S1_WD, m0, n0w, i, j, acc);
#pragma unroll
    for (int nt = 0; nt < 8; nt++) {
        int c = n0w + nt * 8 + 2 * tig;
        *reinterpret_cast<uint32_t*>(g_dstp + (size_t)node0 * HID + c) =
            pack_h2(acc[nt * 4 + 0] + b1v[nt].x, acc[nt * 4 + 1] + b1v[nt].y);
        *reinterpret_cast<uint32_t*>(g_dstp + (size_t)(node0 + 8) * HID + c) =
            pack_h2(acc[nt * 4 + 2] + b1v[nt].x, acc[nt * 4 + 3] + b1v[nt].y);
    }
}

// ==========================================================================
// K2: persistent fused edge kernel
// ==========================================================================
#define S2_B2 0
#define S2_G  512
#define S2_BE 1024
#define S2_RS 1536
#define S2_RQ 3584
#define S2_WE 8192
#define S2_W2 40960
#define S2_A1 73728
#define S2_A2 106496
#define S2_D  139264
#define SMEM2 204800

extern "C" __global__ void __launch_bounds__(512, 1)
k2_edge(const float* __restrict__ efeat,
        const int* __restrict__ src_idx, const int* __restrict__ dst_idx,
        const float* __restrict__ w_e, const float* __restrict__ w2,
        const float* __restrict__ b2, const float* __restrict__ gamma,
        const float* __restrict__ beta,
        float* __restrict__ out, int E, int n_tiles) {
    extern __shared__ char smem[];
    const int tid = threadIdx.x;
    const int w = tid >> 5, lane = tid & 31;
    uint32_t sbase = smem_u32(smem);

    for (int q = tid; q < HID; q += 512) {
        reinterpret_cast<float*>(smem + S2_B2)[q] = b2[q];
        reinterpret_cast<float*>(smem + S2_G)[q]  = gamma[q];
        reinterpret_cast<float*>(smem + S2_BE)[q] = beta[q];
    }
    fill_tile(smem + S2_WE, w_e, 0, HID - 1, tid);
    fill_tile(smem + S2_W2, w2, 0, HID - 1, tid);

    const int t0 = blockIdx.x;
    if (t0 < n_tiles)
        fill_tile(smem + S2_A1, efeat, t0 << 7, E - 1, tid);
    __syncthreads();

    const int gID = lane >> 2, tig = lane & 3;
    const int i = lane & 7, j = lane >> 3;
    const int m0 = (w & 7) * 16, n0w = (w >> 3) * 64;

    // row-phase mapping: 128 rows x 4 col-groups of 32
    const int rr = tid & 127;
    const int cg = tid >> 7;
    const int cb = cg * 32;

    float* RS = reinterpret_cast<float*>(smem + S2_RS);
    float* RQ = reinterpret_cast<float*>(smem + S2_RQ);

    for (int t = t0; t < n_tiles; t += gridDim.x) {
        const int e0 = t << 7;
        float acc[32];

        // ---- GEMM1: efeat @ w_e^T -> D1 (swizzled fp32 smem) ----
        warp_gemm(sbase, S2_A1, S2_WE, m0, n0w, i, j, acc);
#pragma unroll
        for (int nt = 0; nt < 8; nt++) {
            int c = n0w + nt * 8 + 2 * tig;
            STSV2(sbase + S2_D + dsw(m0 + gID,     c), acc[nt * 4 + 0], acc[nt * 4 + 1]);
            STSV2(sbase + S2_D + dsw(m0 + gID + 8, c), acc[nt * 4 + 2], acc[nt * 4 + 3]);
        }
        __syncthreads();

        // ---- row phase: gather + add + SiLU -> A2 ; prefetch next A1 ----
        {
            const int e = e0 + rr;
            const int ec = (e < E) ? e : (E - 1);
            const int si = src_idx[ec];
            const int di = dst_idx[ec];
            const uint4* sp = reinterpret_cast<const uint4*>(g_srcp + (size_t)si * HID + cb);
            const uint4* dp = reinterpret_cast<const uint4*>(g_dstp + (size_t)di * HID + cb);
            uint4 sv[4], dv[4];
#pragma unroll
            for (int k = 0; k < 4; k++) { sv[k] = sp[k]; dv[k] = dp[k]; }

            // overlap next tile's efeat load with gather latency
            const int tn = t + gridDim.x;
            if (tn < n_tiles)
                fill_tile(smem + S2_A1, efeat, tn << 7, E - 1, tid);

#pragma unroll
            for (int q = 0; q < 4; q++) {           // 8 cols per q
                const uint32_t* su = reinterpret_cast<const uint32_t*>(&sv[q]);
                const uint32_t* du = reinterpret_cast<const uint32_t*>(&dv[q]);
                float hq[8];
#pragma unroll
                for (int half4 = 0; half4 < 2; half4++) {   // float4 of D1
                    int c4 = (cb >> 2) + q * 2 + half4;
                    uint32_t unit = (uint32_t)((c4 ^ (rr & 7)) & 31);
                    float4 dfrag = *reinterpret_cast<const float4*>(
                        smem + S2_D + rr * 512 + unit * 16);
                    float2 s0 = __half22float2(*reinterpret_cast<const __half2*>(&su[half4 * 2 + 0]));
                    float2 s1 = __half22float2(*reinterpret_cast<const __half2*>(&su[half4 * 2 + 1]));
                    float2 d0 = __half22float2(*reinterpret_cast<const __half2*>(&du[half4 * 2 + 0]));
                    float2 d1 = __half22float2(*reinterpret_cast<const __half2*>(&du[half4 * 2 + 1]));
                    hq[half4 * 4 + 0] = dfrag.x + s0.x + d0.x;
                    hq[half4 * 4 + 1] = dfrag.y + s0.y + d0.y;
                    hq[half4 * 4 + 2] = dfrag.z + s1.x + d1.x;
                    hq[half4 * 4 + 3] = dfrag.w + s1.y + d1.y;
                }
                uint4 pk;
                pk.x = pack_h2(silu_f(hq[0]), silu_f(hq[1]));
                pk.y = pack_h2(silu_f(hq[2]), silu_f(hq[3]));
                pk.z = pack_h2(silu_f(hq[4]), silu_f(hq[5]));
                pk.w = pack_h2(silu_f(hq[6]), silu_f(hq[7]));
                int col = cb + q * 8;
                uint32_t off = (uint32_t)(((rr >> 3) + (col >> 6) * 16) * 1024
                                          + (rr & 7) * 128 + (col & 63) * 2);
                off ^= (off >> 3) & 0x70;
                *reinterpret_cast<uint4*>(smem + S2_A2 + off) = pk;
            }
        }
        __syncthreads();

        // ---- GEMM2: silu(sum) @ w2^T -> D2 ----
        warp_gemm(sbase, S2_A2, S2_W2, m0, n0w, i, j, acc);
#pragma unroll
        for (int nt = 0; nt < 8; nt++) {
            int c = n0w + nt * 8 + 2 * tig;
            STSV2(sbase + S2_D + dsw(m0 + gID,     c), acc[nt * 4 + 0], acc[nt * 4 + 1]);
            STSV2(sbase + S2_D + dsw(m0 + gID + 8, c), acc[nt * 4 + 2], acc[nt * 4 + 3]);
        }
        __syncthreads();

        // ---- LN phase ----
        {
            float hb[32];
            float s = 0.f, q = 0.f;
            const float* b2p = reinterpret_cast<const float*>(smem + S2_B2) + cb;
#pragma unroll
            for (int jj = 0; jj < 8; jj++) {
                int c4 = (cb >> 2) + jj;
                uint32_t unit = (uint32_t)((c4 ^ (rr & 7)) & 31);
                float4 dfrag = *reinterpret_cast<const float4*>(
                    smem + S2_D + rr * 512 + unit * 16);
                float x0 = dfrag.x + b2p[jj * 4 + 0];
                float x1 = dfrag.y + b2p[jj * 4 + 1];
                float x2 = dfrag.z + b2p[jj * 4 + 2];
                float x3 = dfrag.w + b2p[jj * 4 + 3];
                hb[jj * 4 + 0] = x0; hb[jj * 4 + 1] = x1;
                hb[jj * 4 + 2] = x2; hb[jj * 4 + 3] = x3;
                s += x0 + x1 + x2 + x3;
                q += x0 * x0 + x1 * x1 + x2 * x2 + x3 * x3;
            }
            RS[cg * 128 + rr] = s;
            RQ[cg * 128 + rr] = q;
            __syncthreads();
            float S = RS[rr] + RS[128 + rr] + RS[256 + rr] + RS[384 + rr];
            float Q = RQ[rr] + RQ[128 + rr] + RQ[256 + rr] + RQ[384 + rr];
            float mu  = S * (1.0f / 128.0f);
            float var = Q * (1.0f / 128.0f) - mu * mu;
            float rsg = rsqrtf(var + 1e-5f);

            const int e = e0 + rr;
            if (e < E) {
                const float* gp = reinterpret_cast<const float*>(smem + S2_G)  + cb;
                const float* bp = reinterpret_cast<const float*>(smem + S2_BE) + cb;
                float4* op = reinterpret_cast<float4*>(out + (size_t)e * HID + cb);
#pragma unroll
                for (int jj = 0; jj < 8; jj++) {
                    float4 o;
                    o.x = (hb[jj * 4 + 0] - mu) * rsg * gp[jj * 4 + 0] + bp[jj * 4 + 0];
                    o.y = (hb[jj * 4 + 1] - mu) * rsg * gp[jj * 4 + 1] + bp[jj * 4 + 1];
                    o.z = (hb[jj * 4 + 2] - mu) * rsg * gp[jj * 4 + 2] + bp[jj * 4 + 2];
                    o.w = (hb[jj * 4 + 3] - mu) * rsg * gp[jj * 4 + 3] + bp[jj * 4 + 3];
                    op[jj] = o;
                }
            }
        }
        __syncthreads();  // D, RS/RQ, A1 safe for next iteration
    }
}

// ==========================================================================
// Launch
// ==========================================================================
extern "C" void kernel_launch(void* const* d_in, const int* in_sizes, int n_in,
                              void* d_out, int out_size) {
    if (n_in < 13) return;
    const float* efeat    = (const float*)d_in[0];
    const float* src_feat = (const float*)d_in[1];
    const float* dst_feat = (const float*)d_in[2];
    const int*   src_idx  = (const int*)d_in[3];
    const int*   dst_idx  = (const int*)d_in[4];
    const float* w_e      = (const float*)d_in[5];
    const float* w_src    = (const float*)d_in[6];
    const float* w_dst    = (const float*)d_in[7];
    const float* b1       = (const float*)d_in[8];
    const float* w2       = (const float*)d_in[9];
    const float* b2       = (const float*)d_in[10];
    const float* gamma    = (const float*)d_in[11];
    const float* beta     = (const float*)d_in[12];

    int E  = in_sizes[0] / HID;
    int Nn = in_sizes[1] / HID;
    int nt1 = (Nn + 127) / 128;
    int nt2 = (E + 127) / 128;

    cudaFuncSetAttribute(k1_nodes, cudaFuncAttributeMaxDynamicSharedMemorySize, SMEM1);
    cudaFuncSetAttribute(k2_edge,  cudaFuncAttributeMaxDynamicSharedMemorySize, SMEM2);

    k1_nodes<<<nt1, 512, SMEM1>>>(src_feat, dst_feat, w_src, w_dst, b1, Nn);

    int grid2 = nt2 < 148 ? nt2 : 148;
    k2_edge<<<grid2, 512, SMEM2>>>(efeat, src_idx, dst_idx, w_e, w2, b2,
                                   gamma, beta, (float*)d_out, E, nt2);
}

// round 10
// speedup vs baseline: 1.0285x; 1.0285x over previous
#include <cuda_runtime.h>
#include <cuda_fp16.h>
#include <cstdint>
#include <cstddef>

// ==========================================================================
// TruncatedMLP fused edge MLP for GB300 (sm_103a harness, base sm_103 PTX)
//   Tensor cores via warp-level mma.sync m16n8k16 (f32.f16.f16.f32) + ldmatrix.
//   R10 == R9 (frozen; three audit passes clean). Measured base: R6 = 813us,
//   L1=59.9% top pipe. R9 removes ~3.2K of ~11.4K L1 wavefronts/tile:
//     - 32x32 warp tiles (LDSM 40 -> 32 per warp-GEMM)
//     - row phase: warp = 2 edges x 16 chunks -> full-row coalesced gathers;
//       idx loads issued before the A1 prefetch (dependent-chain head first)
//     - shfl-based LN with row-contiguous smem reads + stores
//   No further unverified deltas until a bench lands (3 stacked already).
// ==========================================================================

#define HID 128
#define MAX_NODES_PAD 131072

__device__ __align__(256) __half g_srcp[(size_t)MAX_NODES_PAD * HID];
__device__ __align__(256) __half g_dstp[(size_t)MAX_NODES_PAD * HID];

// ---------------- helpers ----------------
__device__ __forceinline__ uint32_t smem_u32(const void* p) {
    uint32_t a;
    asm("{ .reg .u64 t; cvta.to.shared.u64 t, %1; cvt.u32.u64 %0, t; }" : "=r"(a) : "l"(p));
    return a;
}

#define LDSM4(r, addr)                                                              \
    asm volatile("ldmatrix.sync.aligned.m8n8.x4.shared.b16 {%0,%1,%2,%3}, [%4];"    \
        : "=r"((r)[0]), "=r"((r)[1]), "=r"((r)[2]), "=r"((r)[3]) : "r"(addr))

#define MMA16816(d, a, b0, b1)                                                      \
    asm volatile("mma.sync.aligned.m16n8k16.row.col.f32.f16.f16.f32 "               \
        "{%0,%1,%2,%3}, {%4,%5,%6,%7}, {%8,%9}, {%0,%1,%2,%3};"                     \
        : "+f"((d)[0]), "+f"((d)[1]), "+f"((d)[2]), "+f"((d)[3])                    \
        : "r"((a)[0]), "r"((a)[1]), "r"((a)[2]), "r"((a)[3]), "r"(b0), "r"(b1))

#define STSV2(addr, x, y)                                                           \
    asm volatile("st.shared.v2.f32 [%0], {%1,%2};" :: "r"(addr), "f"(x), "f"(y) : "memory")

__device__ __forceinline__ uint32_t pack_h2(float a, float b) {
    __half2 h = __floats2half2_rn(a, b);
    return *reinterpret_cast<uint32_t*>(&h);
}

__device__ __forceinline__ float silu_f(float x) {
    float t;
    asm("ex2.approx.f32 %0, %1;" : "=f"(t) : "f"(-1.4426950408889634f * x));
    float d = 1.0f + t;
    float r;
    asm("rcp.approx.f32 %0, %1;" : "=f"(r) : "f"(d));
    return x * r;
}

// Blocked SW128 fp16 tile addressing (16B units), col8 = col/8 in halves.
__device__ __forceinline__ uint32_t sw_off(int row, int col8) {
    uint32_t off = (uint32_t)(((row >> 3) + (col8 >> 3) * 16) * 1024
                              + (row & 7) * 128 + (col8 & 7) * 16);
    return off ^ ((off >> 3) & 0x70);
}

// D (fp32 128x128) smem: byte addr = r*512 + (((c>>2) ^ (r&7))&31)*16 + (c&3)*4
__device__ __forceinline__ uint32_t dsw(int r, int c) {
    return (uint32_t)(r * 512 + ((((c >> 2) ^ (r & 7)) & 31) << 4) + (c & 3) * 4);
}

// Fill a 128x128 fp16 blocked SW128 smem tile from row-major fp32 (ld=128).
__device__ __forceinline__ void fill_tile(char* tile, const float* __restrict__ gsrc,
                                          int row0, int max_row, int tid) {
#pragma unroll
    for (int j = 0; j < 8; j++) {
        int v = j * 512 + tid;
        int row = v >> 5;
        int c4  = v & 31;
        int r = row0 + row;
        if (r > max_row) r = max_row;
        float4 f = reinterpret_cast<const float4*>(gsrc + (size_t)r * HID)[c4];
        uint32_t u0 = pack_h2(f.x, f.y);
        uint32_t u1 = pack_h2(f.z, f.w);
        uint32_t off = (uint32_t)(((row >> 3) + (c4 >> 4) * 16) * 1024
                                  + (row & 7) * 128 + (c4 & 15) * 8);
        off ^= (off >> 3) & 0x70;
        *reinterpret_cast<uint64_t*>(tile + off) = ((uint64_t)u1 << 32) | u0;
    }
}

// Warp GEMM: 32 rows x 32 cols, K=128. acc[32]: [mt(2)][ntp(4)][4].
// Rows: m0 + mt*16 + {gID, gID+8}; cols: n0w + ntp*8 + 2*tig.
__device__ __forceinline__ void warp_gemm(uint32_t sbase, uint32_t aoff, uint32_t woff,
                                          int m0, int n0w, int i, int j, float* acc) {
#pragma unroll
    for (int z = 0; z < 32; z++) acc[z] = 0.0f;
    const int arow = i + (j & 1) * 8;
    const int brow = i + (j >> 1) * 8;
#pragma unroll
    for (int ks = 0; ks < 8; ks++) {
        uint32_t a0[4], a1[4], b0[4], b1[4];
        LDSM4(a0, sbase + aoff + sw_off(m0 +      arow, ks * 2 + (j >> 1)));
        LDSM4(a1, sbase + aoff + sw_off(m0 + 16 + arow, ks * 2 + (j >> 1)));
        LDSM4(b0, sbase + woff + sw_off(n0w +      brow, ks * 2 + (j & 1)));
        LDSM4(b1, sbase + woff + sw_off(n0w + 16 + brow, ks * 2 + (j & 1)));
        MMA16816(acc + 0,  a0, b0[0], b0[1]);
        MMA16816(acc + 4,  a0, b0[2], b0[3]);
        MMA16816(acc + 8,  a0, b1[0], b1[1]);
        MMA16816(acc + 12, a0, b1[2], b1[3]);
        MMA16816(acc + 16, a1, b0[0], b0[1]);
        MMA16816(acc + 20, a1, b0[2], b0[3]);
        MMA16816(acc + 24, a1, b1[0], b1[1]);
        MMA16816(acc + 28, a1, b1[2], b1[3]);
    }
}

// ==========================================================================
// K1: node projections -> fp16 scratch tables
// ==========================================================================
#define S1_B1 0
#define S1_WS 1024
#define S1_WD 33792
#define S1_AS 66560
#define S1_AD 99328
#define SMEM1 132096

extern "C" __global__ void __launch_bounds__(512, 1)
k1_nodes(const float* __restrict__ src_feat, const float* __restrict__ dst_feat,
         const float* __restrict__ w_src, const float* __restrict__ w_dst,
         const float* __restrict__ b1, int Nn) {
    extern __shared__ char smem[];
    const int tid = threadIdx.x;
    const int w = tid >> 5, lane = tid & 31;
    uint32_t sbase = smem_u32(smem);

    for (int q = tid; q < HID; q += 512)
        reinterpret_cast<float*>(smem + S1_B1)[q] = b1[q];
    const int n0 = blockIdx.x << 7;
    fill_tile(smem + S1_WS, w_src, 0, HID - 1, tid);
    fill_tile(smem + S1_WD, w_dst, 0, HID - 1, tid);
    fill_tile(smem + S1_AS, src_feat, n0, Nn - 1, tid);
    fill_tile(smem + S1_AD, dst_feat, n0, Nn - 1, tid);
    __syncthreads();

    const int gID = lane >> 2, tig = lane & 3;
    const int i = lane & 7, j = lane >> 3;
    const int m0 = (w & 3) * 32, n0w = (w >> 2) * 32;

    float2 b1v[4];
#pragma unroll
    for (int nt = 0; nt < 4; nt++) {
        int c = n0w + nt * 8 + 2 * tig;
        b1v[nt] = *reinterpret_cast<const float2*>(smem + S1_B1 + c * 4);
    }

    float acc[32];

    warp_gemm(sbase, S1_AS, S1_WS, m0, n0w, i, j, acc);
#pragma unroll
    for (int mt = 0; mt < 2; mt++) {
        const int node0 = n0 + m0 + mt * 16 + gID;
#pragma unroll
        for (int nt = 0; nt < 4; nt++) {
            int c = n0w + nt * 8 + 2 * tig;
            const float* a = acc + mt * 16 + nt * 4;
            *reinterpret_cast<uint32_t*>(g_srcp + (size_t)node0 * HID + c) =
                pack_h2(a[0], a[1]);
            *reinterpret_cast<uint32_t*>(g_srcp + (size_t)(node0 + 8) * HID + c) =
                pack_h2(a[2], a[3]);
        }
    }

    warp_gemm(sbase, S1_AD, S1_WD, m0, n0w, i, j, acc);
#pragma unroll
    for (int mt = 0; mt < 2; mt++) {
        const int node0 = n0 + m0 + mt * 16 + gID;
#pragma unroll
        for (int nt = 0; nt < 4; nt++) {
            int c = n0w + nt * 8 + 2 * tig;
            const float* a = acc + mt * 16 + nt * 4;
            *reinterpret_cast<uint32_t*>(g_dstp + (size_t)node0 * HID + c) =
                pack_h2(a[0] + b1v[nt].x, a[1] + b1v[nt].y);
            *reinterpret_cast<uint32_t*>(g_dstp + (size_t)(node0 + 8) * HID + c) =
                pack_h2(a[2] + b1v[nt].x, a[3] + b1v[nt].y);
        }
    }
}

// ==========================================================================
// K2: persistent fused edge kernel
// ==========================================================================
#define S2_B2 0
#define S2_G  512
#define S2_BE 1024
#define S2_WE 8192
#define S2_W2 40960
#define S2_A1 73728
#define S2_A2 106496
#define S2_D  139264
#define SMEM2 204800

extern "C" __global__ void __launch_bounds__(512, 1)
k2_edge(const float* __restrict__ efeat,
        const int* __restrict__ src_idx, const int* __restrict__ dst_idx,
        const float* __restrict__ w_e, const float* __restrict__ w2,
        const float* __restrict__ b2, const float* __restrict__ gamma,
        const float* __restrict__ beta,
        float* __restrict__ out, int E, int n_tiles) {
    extern __shared__ char smem[];
    const int tid = threadIdx.x;
    const int w = tid >> 5, lane = tid & 31;
    uint32_t sbase = smem_u32(smem);

    for (int q = tid; q < HID; q += 512) {
        reinterpret_cast<float*>(smem + S2_B2)[q] = b2[q];
        reinterpret_cast<float*>(smem + S2_G)[q]  = gamma[q];
        reinterpret_cast<float*>(smem + S2_BE)[q] = beta[q];
    }
    fill_tile(smem + S2_WE, w_e, 0, HID - 1, tid);
    fill_tile(smem + S2_W2, w2, 0, HID - 1, tid);

    const int t0 = blockIdx.x;
    if (t0 < n_tiles)
        fill_tile(smem + S2_A1, efeat, t0 << 7, E - 1, tid);
    __syncthreads();

    const int gID = lane >> 2, tig = lane & 3;
    const int i = lane & 7, j = lane >> 3;
    const int m0 = (w & 3) * 32, n0w = (w >> 2) * 32;

    // Row phase: warp = 2 edges x 16 chunks per sub-iteration k.
    const int half = lane >> 4;      // which of the 2 edges
    const int c16  = lane & 15;      // 16B chunk = 8 halves, cols c16*8..+7

    // LN/store lane constants (cols lane*4 .. lane*4+3)
    const float4 b2v = *reinterpret_cast<const float4*>(smem + S2_B2 + lane * 16);
    const float4 gv  = *reinterpret_cast<const float4*>(smem + S2_G  + lane * 16);
    const float4 bev = *reinterpret_cast<const float4*>(smem + S2_BE + lane * 16);

    for (int t = t0; t < n_tiles; t += gridDim.x) {
        const int e0 = t << 7;
        float acc[32];

        // ---- GEMM1: efeat @ w_e^T -> D1 (swizzled fp32 smem) ----
        warp_gemm(sbase, S2_A1, S2_WE, m0, n0w, i, j, acc);
#pragma unroll
        for (int mt = 0; mt < 2; mt++) {
            const int r0 = m0 + mt * 16 + gID;
#pragma unroll
            for (int nt = 0; nt < 4; nt++) {
                int c = n0w + nt * 8 + 2 * tig;
                const float* a = acc + mt * 16 + nt * 4;
                STSV2(sbase + S2_D + dsw(r0,     c), a[0], a[1]);
                STSV2(sbase + S2_D + dsw(r0 + 8, c), a[2], a[3]);
            }
        }
        __syncthreads();

        // ---- row phase: idx first, A1 prefetch overlaps, coalesced gathers ----
        {
            // dependent-chain head: issue all idx loads first
            int si[4], di[4];
#pragma unroll
            for (int k = 0; k < 4; k++) {
                const int er = w * 8 + 2 * k + half;
                const int e = e0 + er;
                const int ec = (e < E) ? e : (E - 1);
                si[k] = src_idx[ec];
                di[k] = dst_idx[ec];
            }

            // independent prefetch overlaps idx->gather latency
            const int tn = t + gridDim.x;
            if (tn < n_tiles)
                fill_tile(smem + S2_A1, efeat, tn << 7, E - 1, tid);

            uint4 sv[4], dv[4];
#pragma unroll
            for (int k = 0; k < 4; k++) {
                sv[k] = *reinterpret_cast<const uint4*>(g_srcp + (size_t)si[k] * HID + c16 * 8);
                dv[k] = *reinterpret_cast<const uint4*>(g_dstp + (size_t)di[k] * HID + c16 * 8);
            }

#pragma unroll
            for (int k = 0; k < 4; k++) {
                const int er = w * 8 + 2 * k + half;
                // D1 cols c16*8..+7 -> two float4 at c4 = c16*2, c16*2+1
                const int c4a = c16 * 2;
                uint32_t ua = (uint32_t)((c4a ^ (er & 7)) & 31);
                uint32_t ub = (uint32_t)(((c4a + 1) ^ (er & 7)) & 31);
                float4 d0 = *reinterpret_cast<const float4*>(smem + S2_D + er * 512 + ua * 16);
                float4 d1 = *reinterpret_cast<const float4*>(smem + S2_D + er * 512 + ub * 16);
                const uint32_t* su = reinterpret_cast<const uint32_t*>(&sv[k]);
                const uint32_t* du = reinterpret_cast<const uint32_t*>(&dv[k]);
                float2 s0 = __half22float2(*reinterpret_cast<const __half2*>(&su[0]));
                float2 s1 = __half22float2(*reinterpret_cast<const __half2*>(&su[1]));
                float2 s2 = __half22float2(*reinterpret_cast<const __half2*>(&su[2]));
                float2 s3 = __half22float2(*reinterpret_cast<const __half2*>(&su[3]));
                float2 g0 = __half22float2(*reinterpret_cast<const __half2*>(&du[0]));
                float2 g1 = __half22float2(*reinterpret_cast<const __half2*>(&du[1]));
                float2 g2 = __half22float2(*reinterpret_cast<const __half2*>(&du[2]));
                float2 g3 = __half22float2(*reinterpret_cast<const __half2*>(&du[3]));
                uint4 pk;
                pk.x = pack_h2(silu_f(d0.x + s0.x + g0.x), silu_f(d0.y + s0.y + g0.y));
                pk.y = pack_h2(silu_f(d0.z + s1.x + g1.x), silu_f(d0.w + s1.y + g1.y));
                pk.z = pack_h2(silu_f(d1.x + s2.x + g2.x), silu_f(d1.y + s2.y + g2.y));
                pk.w = pack_h2(silu_f(d1.z + s3.x + g3.x), silu_f(d1.w + s3.y + g3.y));
                *reinterpret_cast<uint4*>(smem + S2_A2 + sw_off(er, c16)) = pk;
            }
        }
        __syncthreads();

        // ---- GEMM2: silu(sum) @ w2^T -> D2 ----
        warp_gemm(sbase, S2_A2, S2_W2, m0, n0w, i, j, acc);
#pragma unroll
        for (int mt = 0; mt < 2; mt++) {
            const int r0 = m0 + mt * 16 + gID;
#pragma unroll
            for (int nt = 0; nt < 4; nt++) {
                int c = n0w + nt * 8 + 2 * tig;
                const float* a = acc + mt * 16 + nt * 4;
                STSV2(sbase + S2_D + dsw(r0,     c), a[0], a[1]);
                STSV2(sbase + S2_D + dsw(r0 + 8, c), a[2], a[3]);
            }
        }
        __syncthreads();

        // ---- LN + store: warp w owns rows w*8..w*8+7; lane owns 4 cols ----
#pragma unroll
        for (int jj = 0; jj < 8; jj++) {
            const int r = w * 8 + jj;
            uint32_t unit = (uint32_t)((lane ^ (r & 7)) & 31);
            float4 d = *reinterpret_cast<const float4*>(smem + S2_D + r * 512 + unit * 16);
            float hx = d.x + b2v.x, hy = d.y + b2v.y;
            float hz = d.z + b2v.z, hw = d.w + b2v.w;
            float s = hx + hy + hz + hw;
            float q = hx * hx + hy * hy + hz * hz + hw * hw;
#pragma unroll
            for (int off = 16; off > 0; off >>= 1) {
                s += __shfl_xor_sync(0xFFFFFFFFu, s, off);
                q += __shfl_xor_sync(0xFFFFFFFFu, q, off);
            }
            float mu  = s * (1.0f / 128.0f);
            float var = q * (1.0f / 128.0f) - mu * mu;
            float rsg = rsqrtf(var + 1e-5f);
            const int e = e0 + r;
            if (e < E) {
                float4 o;
                o.x = (hx - mu) * rsg * gv.x + bev.x;
                o.y = (hy - mu) * rsg * gv.y + bev.y;
                o.z = (hz - mu) * rsg * gv.z + bev.z;
                o.w = (hw - mu) * rsg * gv.w + bev.w;
                *reinterpret_cast<float4*>(out + (size_t)e * HID + lane * 4) = o;
            }
        }
        __syncthreads();  // D, A1 safe for next iteration
    }
}

// ==========================================================================
// Launch
// ==========================================================================
extern "C" void kernel_launch(void* const* d_in, const int* in_sizes, int n_in,
                              void* d_out, int out_size) {
    if (n_in < 13) return;
    const float* efeat    = (const float*)d_in[0];
    const float* src_feat = (const float*)d_in[1];
    const float* dst_feat = (const float*)d_in[2];
    const int*   src_idx  = (const int*)d_in[3];
    const int*   dst_idx  = (const int*)d_in[4];
    const float* w_e      = (const float*)d_in[5];
    const float* w_src    = (const float*)d_in[6];
    const float* w_dst    = (const float*)d_in[7];
    const float* b1       = (const float*)d_in[8];
    const float* w2       = (const float*)d_in[9];
    const float* b2       = (const float*)d_in[10];
    const float* gamma    = (const float*)d_in[11];
    const float* beta     = (const float*)d_in[12];

    int E  = in_sizes[0] / HID;
    int Nn = in_sizes[1] / HID;
    int nt1 = (Nn + 127) / 128;
    int nt2 = (E + 127) / 128;

    cudaFuncSetAttribute(k1_nodes, cudaFuncAttributeMaxDynamicSharedMemorySize, SMEM1);
    cudaFuncSetAttribute(k2_edge,  cudaFuncAttributeMaxDynamicSharedMemorySize, SMEM2);

    k1_nodes<<<nt1, 512, SMEM1>>>(src_feat, dst_feat, w_src, w_dst, b1, Nn);

    int grid2 = nt2 < 148 ? nt2 : 148;
    k2_edge<<<grid2, 512, SMEM2>>>(efeat, src_idx, dst_idx, w_e, w2, b2,
                                   gamma, beta, (float*)d_out, E, nt2);
}

// round 15
// speedup vs baseline: 1.7006x; 1.6535x over previous
#include <cuda_runtime.h>
#include <cuda_fp16.h>
#include <cstdint>
#include <cstddef>

// ==========================================================================
// TruncatedMLP fused edge MLP for GB300 (sm_103a harness, base sm_103 PTX)
//   Tensor cores via warp-level mma.sync m16n8k16 (f32.f16.f16.f32) + ldmatrix.
//   R15 = frozen R11-K2 (occupancy hypothesis, five audits) + K1 restructured
//   on the SAME hypothesis: 256-thr CTAs, one projection per CTA, 65KB smem,
//   launch_bounds(256,2) -> 2 CTAs/SM (512x128 regs = full RF made K1
//   single-CTA before). K1/K2 deltas are separable in per-kernel ncu rows.
// ==========================================================================

#define HID 128
#define MAX_NODES_PAD 131072

__device__ __align__(256) __half g_srcp[(size_t)MAX_NODES_PAD * HID];
__device__ __align__(256) __half g_dstp[(size_t)MAX_NODES_PAD * HID];

// ---------------- helpers ----------------
__device__ __forceinline__ uint32_t smem_u32(const void* p) {
    uint32_t a;
    asm("{ .reg .u64 t; cvta.to.shared.u64 t, %1; cvt.u32.u64 %0, t; }" : "=r"(a) : "l"(p));
    return a;
}

#define LDSM4(r, addr)                                                              \
    asm volatile("ldmatrix.sync.aligned.m8n8.x4.shared.b16 {%0,%1,%2,%3}, [%4];"    \
        : "=r"((r)[0]), "=r"((r)[1]), "=r"((r)[2]), "=r"((r)[3]) : "r"(addr))

#define MMA16816(d, a, b0, b1)                                                      \
    asm volatile("mma.sync.aligned.m16n8k16.row.col.f32.f16.f16.f32 "               \
        "{%0,%1,%2,%3}, {%4,%5,%6,%7}, {%8,%9}, {%0,%1,%2,%3};"                     \
        : "+f"((d)[0]), "+f"((d)[1]), "+f"((d)[2]), "+f"((d)[3])                    \
        : "r"((a)[0]), "r"((a)[1]), "r"((a)[2]), "r"((a)[3]), "r"(b0), "r"(b1))

__device__ __forceinline__ uint32_t pack_h2(float a, float b) {
    __half2 h = __floats2half2_rn(a, b);
    return *reinterpret_cast<uint32_t*>(&h);
}

__device__ __forceinline__ float silu_f(float x) {
    float t;
    asm("ex2.approx.f32 %0, %1;" : "=f"(t) : "f"(-1.4426950408889634f * x));
    float d = 1.0f + t;
    float r;
    asm("rcp.approx.f32 %0, %1;" : "=f"(r) : "f"(d));
    return x * r;
}

// Blocked SW128 fp16 tile addressing (16B units). ATOMS = rows/8 of the tile.
__device__ __forceinline__ uint32_t sw_off(int row, int col8, int atoms) {
    uint32_t off = (uint32_t)(((row >> 3) + (col8 >> 3) * atoms) * 1024
                              + (row & 7) * 128 + (col8 & 7) * 16);
    return off ^ ((off >> 3) & 0x70);
}

// fp16 D (64x128) smem: byte = r*256 + (((c>>3) ^ (r&7))&15)*16 + (c&7)*2
__device__ __forceinline__ uint32_t dsw16(int r, int c) {
    return (uint32_t)(r * 256 + ((((c >> 3) ^ (r & 7)) & 15) << 4) + (c & 7) * 2);
}

// Fill an fp16 blocked SW128 smem tile from row-major fp32 (ld=128).
template <int ROWS, int THREADS>
__device__ __forceinline__ void fill_tile(char* tile, const float* __restrict__ gsrc,
                                          int row0, int max_row, int tid) {
#pragma unroll
    for (int j = 0; j < (ROWS * 32) / THREADS; j++) {
        int v = j * THREADS + tid;
        int row = v >> 5;
        int c4  = v & 31;
        int r = row0 + row;
        if (r > max_row) r = max_row;
        float4 f = reinterpret_cast<const float4*>(gsrc + (size_t)r * HID)[c4];
        uint32_t u0 = pack_h2(f.x, f.y);
        uint32_t u1 = pack_h2(f.z, f.w);
        uint32_t off = (uint32_t)(((row >> 3) + (c4 >> 4) * (ROWS / 8)) * 1024
                                  + (row & 7) * 128 + (c4 & 15) * 8);
        off ^= (off >> 3) & 0x70;
        *reinterpret_cast<uint64_t*>(tile + off) = ((uint64_t)u1 << 32) | u0;
    }
}

// Warp GEMM: 32 rows x 32 cols, K=128. acc[32]: [mt(2)][ntp(4)][4].
// Rows: m0 + mt*16 + {gID, gID+8}; cols: n0w + ntp*8 + 2*tig.
template <int AATOMS>
__device__ __forceinline__ void warp_gemm(uint32_t sbase, uint32_t aoff, uint32_t woff,
                                          int m0, int n0w, int i, int j, float* acc) {
#pragma unroll
    for (int z = 0; z < 32; z++) acc[z] = 0.0f;
    const int arow = i + (j & 1) * 8;
    const int brow = i + (j >> 1) * 8;
#pragma unroll
    for (int ks = 0; ks < 8; ks++) {
        uint32_t a0[4], a1[4], b0[4], b1[4];
        LDSM4(a0, sbase + aoff + sw_off(m0 +      arow, ks * 2 + (j >> 1), AATOMS));
        LDSM4(a1, sbase + aoff + sw_off(m0 + 16 + arow, ks * 2 + (j >> 1), AATOMS));
        LDSM4(b0, sbase + woff + sw_off(n0w +      brow, ks * 2 + (j & 1), 16));
        LDSM4(b1, sbase + woff + sw_off(n0w + 16 + brow, ks * 2 + (j & 1), 16));
        MMA16816(acc + 0,  a0, b0[0], b0[1]);
        MMA16816(acc + 4,  a0, b0[2], b0[3]);
        MMA16816(acc + 8,  a0, b1[0], b1[1]);
        MMA16816(acc + 12, a0, b1[2], b1[3]);
        MMA16816(acc + 16, a1, b0[0], b0[1]);
        MMA16816(acc + 20, a1, b0[2], b0[3]);
        MMA16816(acc + 24, a1, b1[0], b1[1]);
        MMA16816(acc + 28, a1, b1[2], b1[3]);
    }
}

// ==========================================================================
// K1 (R15): one projection per 256-thread CTA -> 2 CTAs/SM.
//   CTA bid < nt1:  src projection of tile bid      -> g_srcp
//   CTA bid >= nt1: dst projection of tile bid-nt1  -> g_dstp (+b1)
// ==========================================================================
#define S1_B1 0
#define S1_W  1024
#define S1_A  33792
#define SMEM1 66560

extern "C" __global__ void __launch_bounds__(256, 2)
k1_nodes(const float* __restrict__ src_feat, const float* __restrict__ dst_feat,
         const float* __restrict__ w_src, const float* __restrict__ w_dst,
         const float* __restrict__ b1, int Nn, int nt1) {
    extern __shared__ char smem[];
    const int tid = threadIdx.x;
    const int w = tid >> 5, lane = tid & 31;
    uint32_t sbase = smem_u32(smem);

    const int bid = blockIdx.x;
    const bool is_dst = (bid >= nt1);
    const int tile = is_dst ? (bid - nt1) : bid;
    const int n0 = tile << 7;

    const float* feat = is_dst ? dst_feat : src_feat;
    const float* wmat = is_dst ? w_dst : w_src;
    __half* table = is_dst ? g_dstp : g_srcp;

    for (int q = tid; q < HID; q += 256)
        reinterpret_cast<float*>(smem + S1_B1)[q] = is_dst ? b1[q] : 0.0f;
    fill_tile<128, 256>(smem + S1_W, wmat, 0, HID - 1, tid);
    fill_tile<128, 256>(smem + S1_A, feat, n0, Nn - 1, tid);
    __syncthreads();

    const int gID = lane >> 2, tig = lane & 3;
    const int i = lane & 7, j = lane >> 3;
    const int m0 = (w & 3) * 32;

    float acc[32];
#pragma unroll
    for (int pass = 0; pass < 2; pass++) {
        const int n0w = (w >> 2) * 32 + pass * 64;

        float2 b1v[4];
#pragma unroll
        for (int nt = 0; nt < 4; nt++) {
            int c = n0w + nt * 8 + 2 * tig;
            b1v[nt] = *reinterpret_cast<const float2*>(smem + S1_B1 + c * 4);
        }

        warp_gemm<16>(sbase, S1_A, S1_W, m0, n0w, i, j, acc);
#pragma unroll
        for (int mt = 0; mt < 2; mt++) {
            const int node0 = n0 + m0 + mt * 16 + gID;
#pragma unroll
            for (int nt = 0; nt < 4; nt++) {
                int c = n0w + nt * 8 + 2 * tig;
                const float* a = acc + mt * 16 + nt * 4;
                *reinterpret_cast<uint32_t*>(table + (size_t)node0 * HID + c) =
                    pack_h2(a[0] + b1v[nt].x, a[1] + b1v[nt].y);
                *reinterpret_cast<uint32_t*>(table + (size_t)(node0 + 8) * HID + c) =
                    pack_h2(a[2] + b1v[nt].x, a[3] + b1v[nt].y);
            }
        }
    }
}

// ==========================================================================
// K2: persistent fused edge kernel — 256 threads, 64-edge tiles, 2 CTAs/SM
// (frozen R11; five audit passes clean)
// ==========================================================================
#define S2_B2 0
#define S2_G  512
#define S2_BE 1024
#define S2_WE 2048
#define S2_W2 34816
#define S2_A  67584
#define S2_D  83968
#define SMEM2 100352

extern "C" __global__ void __launch_bounds__(256, 2)
k2_edge(const float* __restrict__ efeat,
        const int* __restrict__ src_idx, const int* __restrict__ dst_idx,
        const float* __restrict__ w_e, const float* __restrict__ w2,
        const float* __restrict__ b2, const float* __restrict__ gamma,
        const float* __restrict__ beta,
        float* __restrict__ out, int E, int n_tiles) {
    extern __shared__ char smem[];
    const int tid = threadIdx.x;
    const int w = tid >> 5, lane = tid & 31;
    uint32_t sbase = smem_u32(smem);

    for (int q = tid; q < HID; q += 256) {
        reinterpret_cast<float*>(smem + S2_B2)[q] = b2[q];
        reinterpret_cast<float*>(smem + S2_G)[q]  = gamma[q];
        reinterpret_cast<float*>(smem + S2_BE)[q] = beta[q];
    }
    fill_tile<128, 256>(smem + S2_WE, w_e, 0, HID - 1, tid);
    fill_tile<128, 256>(smem + S2_W2, w2, 0, HID - 1, tid);
    __syncthreads();

    const int gID = lane >> 2, tig = lane & 3;
    const int i = lane & 7, j = lane >> 3;
    const int m0 = (w & 1) * 32, n0w = (w >> 1) * 32;

    // Row phase: warp = 2 edges x 16 chunks per sub-iteration k (k=0..3).
    const int half = lane >> 4;      // which of the 2 edges
    const int c16  = lane & 15;      // 16B chunk = 8 halves, cols c16*8..+7

    // LN/store lane constants (cols lane*4 .. lane*4+3)
    const float4 b2v = *reinterpret_cast<const float4*>(smem + S2_B2 + lane * 16);
    const float4 gv  = *reinterpret_cast<const float4*>(smem + S2_G  + lane * 16);
    const float4 bev = *reinterpret_cast<const float4*>(smem + S2_BE + lane * 16);

    for (int t = blockIdx.x; t < n_tiles; t += gridDim.x) {
        const int e0 = t << 6;   // 64 edges per tile
        float acc[32];

        // ---- fill A with efeat tile (A buffer free: prev GEMM2 done) ----
        fill_tile<64, 256>(smem + S2_A, efeat, e0, E - 1, tid);
        __syncthreads();

        // ---- GEMM1: efeat @ w_e^T -> D1 (fp16 swizzled smem) ----
        warp_gemm<8>(sbase, S2_A, S2_WE, m0, n0w, i, j, acc);
#pragma unroll
        for (int mt = 0; mt < 2; mt++) {
            const int r0 = m0 + mt * 16 + gID;
#pragma unroll
            for (int nt = 0; nt < 4; nt++) {
                int c = n0w + nt * 8 + 2 * tig;
                const float* a = acc + mt * 16 + nt * 4;
                *reinterpret_cast<uint32_t*>(smem + S2_D + dsw16(r0,     c)) = pack_h2(a[0], a[1]);
                *reinterpret_cast<uint32_t*>(smem + S2_D + dsw16(r0 + 8, c)) = pack_h2(a[2], a[3]);
            }
        }
        __syncthreads();

        // ---- row phase: coalesced gathers + add + SiLU -> A (as A2) ----
        {
            int si[4], di[4];
#pragma unroll
            for (int k = 0; k < 4; k++) {
                const int er = w * 8 + 2 * k + half;
                const int e = e0 + er;
                const int ec = (e < E) ? e : (E - 1);
                si[k] = src_idx[ec];
                di[k] = dst_idx[ec];
            }
            uint4 sv[4], dv[4];
#pragma unroll
            for (int k = 0; k < 4; k++) {
                sv[k] = *reinterpret_cast<const uint4*>(g_srcp + (size_t)si[k] * HID + c16 * 8);
                dv[k] = *reinterpret_cast<const uint4*>(g_dstp + (size_t)di[k] * HID + c16 * 8);
            }
#pragma unroll
            for (int k = 0; k < 4; k++) {
                const int er = w * 8 + 2 * k + half;
                uint4 dd = *reinterpret_cast<const uint4*>(
                    smem + S2_D + er * 256 + (((c16 ^ (er & 7)) & 15) << 4));
                const uint32_t* dcu = reinterpret_cast<const uint32_t*>(&dd);
                const uint32_t* su  = reinterpret_cast<const uint32_t*>(&sv[k]);
                const uint32_t* du  = reinterpret_cast<const uint32_t*>(&dv[k]);
                uint4 pk;
                uint32_t* pku = reinterpret_cast<uint32_t*>(&pk);
#pragma unroll
                for (int q = 0; q < 4; q++) {
                    float2 dq = __half22float2(*reinterpret_cast<const __half2*>(&dcu[q]));
                    float2 sq = __half22float2(*reinterpret_cast<const __half2*>(&su[q]));
                    float2 gq = __half22float2(*reinterpret_cast<const __half2*>(&du[q]));
                    pku[q] = pack_h2(silu_f(dq.x + sq.x + gq.x),
                                     silu_f(dq.y + sq.y + gq.y));
                }
                *reinterpret_cast<uint4*>(smem + S2_A + sw_off(er, c16, 8)) = pk;
            }
        }
        __syncthreads();

        // ---- GEMM2: silu(sum) @ w2^T -> D2 (fp16) ----
        warp_gemm<8>(sbase, S2_A, S2_W2, m0, n0w, i, j, acc);
#pragma unroll
        for (int mt = 0; mt < 2; mt++) {
            const int r0 = m0 + mt * 16 + gID;
#pragma unroll
            for (int nt = 0; nt < 4; nt++) {
                int c = n0w + nt * 8 + 2 * tig;
                const float* a = acc + mt * 16 + nt * 4;
                *reinterpret_cast<uint32_t*>(smem + S2_D + dsw16(r0,     c)) = pack_h2(a[0], a[1]);
                *reinterpret_cast<uint32_t*>(smem + S2_D + dsw16(r0 + 8, c)) = pack_h2(a[2], a[3]);
            }
        }
        __syncthreads();

        // ---- LN + store: warp w owns rows w*8..w*8+7; lane owns 4 cols ----
#pragma unroll
        for (int jj = 0; jj < 8; jj++) {
            const int r = w * 8 + jj;
            uint2 dd = *reinterpret_cast<const uint2*>(
                smem + S2_D + r * 256 + ((((lane >> 1) ^ (r & 7)) & 15) << 4)
                + (lane & 1) * 8);
            float2 p0 = __half22float2(*reinterpret_cast<const __half2*>(&dd.x));
            float2 p1 = __half22float2(*reinterpret_cast<const __half2*>(&dd.y));
            float hx = p0.x + b2v.x, hy = p0.y + b2v.y;
            float hz = p1.x + b2v.z, hw = p1.y + b2v.w;
            float s = hx + hy + hz + hw;
            float q = hx * hx + hy * hy + hz * hz + hw * hw;
#pragma unroll
            for (int off = 16; off > 0; off >>= 1) {
                s += __shfl_xor_sync(0xFFFFFFFFu, s, off);
                q += __shfl_xor_sync(0xFFFFFFFFu, q, off);
            }
            float mu  = s * (1.0f / 128.0f);
            float var = q * (1.0f / 128.0f) - mu * mu;
            float rsg = rsqrtf(var + 1e-5f);
            const int e = e0 + r;
            if (e < E) {
                float4 o;
                o.x = (hx - mu) * rsg * gv.x + bev.x;
                o.y = (hy - mu) * rsg * gv.y + bev.y;
                o.z = (hz - mu) * rsg * gv.z + bev.z;
                o.w = (hw - mu) * rsg * gv.w + bev.w;
                *reinterpret_cast<float4*>(out + (size_t)e * HID + lane * 4) = o;
            }
        }
        __syncthreads();  // D and A safe for next iteration
    }
}

// ==========================================================================
// Launch
// ==========================================================================
extern "C" void kernel_launch(void* const* d_in, const int* in_sizes, int n_in,
                              void* d_out, int out_size) {
    if (n_in < 13) return;
    const float* efeat    = (const float*)d_in[0];
    const float* src_feat = (const float*)d_in[1];
    const float* dst_feat = (const float*)d_in[2];
    const int*   src_idx  = (const int*)d_in[3];
    const int*   dst_idx  = (const int*)d_in[4];
    const float* w_e      = (const float*)d_in[5];
    const float* w_src    = (const float*)d_in[6];
    const float* w_dst    = (const float*)d_in[7];
    const float* b1       = (const float*)d_in[8];
    const float* w2       = (const float*)d_in[9];
    const float* b2       = (const float*)d_in[10];
    const float* gamma    = (const float*)d_in[11];
    const float* beta     = (const float*)d_in[12];

    int E  = in_sizes[0] / HID;
    int Nn = in_sizes[1] / HID;
    int nt1 = (Nn + 127) / 128;
    int nt2 = (E + 63) / 64;

    cudaFuncSetAttribute(k1_nodes, cudaFuncAttributeMaxDynamicSharedMemorySize, SMEM1);
    cudaFuncSetAttribute(k2_edge,  cudaFuncAttributeMaxDynamicSharedMemorySize, SMEM2);

    k1_nodes<<<nt1 * 2, 256, SMEM1>>>(src_feat, dst_feat, w_src, w_dst, b1, Nn, nt1);

    int grid2 = nt2 < 296 ? nt2 : 296;   // 2 CTAs x 148 SMs
    k2_edge<<<grid2, 256, SMEM2>>>(efeat, src_idx, dst_idx, w_e, w2, b2,
                                   gamma, beta, (float*)d_out, E, nt2);
}